// round 1
// baseline (speedup 1.0000x reference)
#include <cuda_runtime.h>

typedef unsigned long long ull;

// Problem constants
constexpr int B_ = 8, T_ = 12, H_ = 96, W_ = 96, C_ = 32, F_ = 32, G_ = 128;
constexpr int HW_ = H_ * W_;

// Scratch (device globals -- allocation-free kernel_launch)
__device__ float g_xz[(size_t)B_ * T_ * HW_ * G_];  // precomputed conv(x_t, Wx) + b
__device__ float g_wc[9 * C_ * G_];                 // Wx + Wh
__device__ float g_h0[(size_t)B_ * HW_ * F_];       // h double buffer
__device__ float g_h1[(size_t)B_ * HW_ * F_];
__device__ float g_c[(size_t)B_ * HW_ * F_];        // cell state (in-place safe)

// ---- packed fp32x2 helpers (sm_100+ FFMA2 path) ----
__device__ __forceinline__ ull pack2(float v) {
    ull r;
    asm("mov.b64 %0, {%1, %2};" : "=l"(r) : "f"(v), "f"(v));
    return r;
}
__device__ __forceinline__ void fma2(ull& d, ull a, ull b) {
    asm("fma.rn.f32x2 %0, %1, %2, %3;" : "=l"(d) : "l"(a), "l"(b), "l"(d));
}
__device__ __forceinline__ float2 unp2(ull v) {
    unsigned lo, hi;
    asm("mov.b64 {%0, %1}, %2;" : "=r"(lo), "=r"(hi) : "l"(v));
    return make_float2(__uint_as_float(lo), __uint_as_float(hi));
}

// Prep: Wc = Wx + Wh; zero h buffers and c state.
__global__ void prep_kernel(const float* __restrict__ Wx,
                            const float* __restrict__ Wh) {
    int i = blockIdx.x * blockDim.x + threadIdx.x;
    if (i < 9 * C_ * G_) g_wc[i] = Wx[i] + Wh[i];
    if (i < B_ * HW_ * F_) {
        g_h0[i] = 0.f;
        g_h1[i] = 0.f;
        g_c[i]  = 0.f;
    }
}

// One kernel, two modes:
//   REC=false: xz[n] = conv(x[n], Wx) + bias          (n = b*T + t, 96 images)
//   REC=true : z = xz[b,t] + conv(h_prev, Wc); gates; c,h update; write out
// Block: 128 threads, tile = 1 row x 32 pixels x all 128 couts.
// Thread: 2 pixels x 16 couts as 8 f32x2 pairs each.
template <bool REC>
__global__ __launch_bounds__(128)
void conv_lstm_kernel(const float* __restrict__ in,    // x        (!REC only)
                      const float* __restrict__ wt,    // Wx       (!REC only)
                      const float* __restrict__ bias,  // b        (!REC only)
                      float* __restrict__ dout,        // output   (REC only)
                      int t) {
    __shared__ float s[32 * 128];  // union: input tile (3*34*33=3366) / z tile (4096)

    const int tid = threadIdx.x;
    const int cg  = tid & 7;    // cout group: couts [cg*16, cg*16+16)
    const int pq  = tid >> 3;   // pixel pair index: pixels 2*pq, 2*pq+1
    const int x0  = blockIdx.x * 32;
    const int y   = blockIdx.y;
    const int n   = blockIdx.z;

    const float* hin = (t & 1) ? g_h1 : g_h0;
    float*       hout = (t & 1) ? g_h0 : g_h1;

    const float* img = REC ? (hin + (size_t)n * HW_ * C_)
                           : (in + (size_t)n * HW_ * C_);

    // Stage 3 rows x 34 cols x 32 ch input tile (zero-padded SAME), stride 33 to dodge bank conflicts
    for (int idx = tid; idx < 3 * 34 * 8; idx += 128) {
        int r   = idx / (34 * 8);
        int rem = idx - r * (34 * 8);
        int xh  = rem >> 3;
        int c4  = rem & 7;
        int gy = y - 1 + r, gx = x0 - 1 + xh;
        float4 v = make_float4(0.f, 0.f, 0.f, 0.f);
        if ((unsigned)gy < (unsigned)H_ && (unsigned)gx < (unsigned)W_)
            v = *(const float4*)(img + ((size_t)gy * W_ + gx) * C_ + c4 * 4);
        float* d = &s[(r * 34 + xh) * 33 + c4 * 4];
        d[0] = v.x; d[1] = v.y; d[2] = v.z; d[3] = v.w;
    }
    __syncthreads();

    ull acc[2][8];
#pragma unroll
    for (int p = 0; p < 2; p++)
#pragma unroll
        for (int j = 0; j < 8; j++) acc[p][j] = 0ull;

    const float* wb = (REC ? g_wc : wt) + cg * 16;
    const int px0 = pq * 2;

#pragma unroll
    for (int r = 0; r < 3; r++) {
#pragma unroll
        for (int kx = 0; kx < 3; kx++) {
            const float* s0 = &s[(r * 34 + px0 + kx) * 33];
            const float* wr = wb + (size_t)(r * 3 + kx) * (C_ * G_);
#pragma unroll 4
            for (int ci = 0; ci < C_; ci++) {
                ull a0 = pack2(s0[ci]);
                ull a1 = pack2(s0[33 + ci]);
                const ulonglong2* wq = (const ulonglong2*)(wr + (size_t)ci * G_);
#pragma unroll
                for (int j = 0; j < 4; j++) {
                    ulonglong2 q = wq[j];
                    fma2(acc[0][2 * j],     a0, q.x);
                    fma2(acc[0][2 * j + 1], a0, q.y);
                    fma2(acc[1][2 * j],     a1, q.x);
                    fma2(acc[1][2 * j + 1], a1, q.y);
                }
            }
        }
    }

    if (!REC) {
        // Write conv(x, Wx) + bias to g_xz
        float* op = g_xz + ((size_t)n * HW_ + (size_t)y * W_ + x0) * G_;
#pragma unroll
        for (int p = 0; p < 2; p++) {
            int px = px0 + p;
#pragma unroll
            for (int j = 0; j < 8; j++) {
                float2 v = unp2(acc[p][j]);
                int co = cg * 16 + 2 * j;
                op[(size_t)px * G_ + co]     = v.x + bias[co];
                op[(size_t)px * G_ + co + 1] = v.y + bias[co + 1];
            }
        }
    } else {
        // z = acc + xz  -> shared tile for cross-thread gate access
        __syncthreads();  // done reading input tile
        const float* xzp = g_xz +
            (((size_t)(n * T_ + t) * HW_) + (size_t)y * W_ + x0) * G_;
#pragma unroll
        for (int p = 0; p < 2; p++) {
            int px = px0 + p;
#pragma unroll
            for (int j = 0; j < 8; j++) {
                float2 v = unp2(acc[p][j]);
                int co = cg * 16 + 2 * j;
                s[px * G_ + co]     = v.x + xzp[(size_t)px * G_ + co];
                s[px * G_ + co + 1] = v.y + xzp[(size_t)px * G_ + co + 1];
            }
        }
        __syncthreads();

        // Gates: i,f,c~,o in channel blocks [0,32),[32,64),[64,96),[96,128)
        const size_t cbase = ((size_t)n * HW_ + (size_t)y * W_ + x0) * F_;
        float* outp = dout +
            (((size_t)(n * T_ + t) * HW_) + (size_t)y * W_ + x0) * F_;
#pragma unroll
        for (int k = 0; k < 8; k++) {
            int idx = tid + k * 128;    // 0..1023 = 32 px * 32 f
            int px = idx >> 5;
            int f  = idx & 31;
            float zi = s[px * G_ + f];
            float zf = s[px * G_ + 32 + f];
            float zc = s[px * G_ + 64 + f];
            float zo = s[px * G_ + 96 + f];
            float cold = g_c[cbase + (size_t)px * F_ + f];
            float ig = __saturatef(fmaf(0.2f, zi, 0.5f));
            float fg = __saturatef(fmaf(0.2f, zf, 0.5f));
            float cn = fmaf(fg, cold, ig * tanhf(zc));
            float og = __saturatef(fmaf(0.2f, zo, 0.5f));
            float hn = og * tanhf(cn);
            g_c[cbase + (size_t)px * F_ + f]  = cn;
            hout[cbase + (size_t)px * F_ + f] = hn;
            outp[(size_t)px * F_ + f]         = hn;
        }
    }
}

extern "C" void kernel_launch(void* const* d_in, const int* in_sizes, int n_in,
                              void* d_out, int out_size) {
    const float* x  = (const float*)d_in[0];
    const float* Wx = (const float*)d_in[1];
    const float* Wh = (const float*)d_in[2];
    const float* b  = (const float*)d_in[3];
    float* out = (float*)d_out;

    // 1) Wc = Wx + Wh, zero states
    prep_kernel<<<(B_ * HW_ * F_ + 255) / 256, 256>>>(Wx, Wh);

    // 2) All 96 input-side convs in parallel: g_xz = conv(x, Wx) + b
    conv_lstm_kernel<false><<<dim3(W_ / 32, H_, B_ * T_), 128>>>(
        x, Wx, b, nullptr, 0);

    // 3) 12 sequential recurrent steps (conv(h, Wc) + gates fused)
    for (int t = 0; t < T_; t++)
        conv_lstm_kernel<true><<<dim3(W_ / 32, H_, B_), 128>>>(
            nullptr, nullptr, nullptr, out, t);
}

// round 5
// speedup vs baseline: 14.1407x; 14.1407x over previous
#include <cuda_runtime.h>
#include <cuda_bf16.h>
#include <cstdint>

constexpr int B_ = 8, T_ = 12, H_ = 96, W_ = 96, C_ = 32, F_ = 32;
constexpr int HW_ = H_ * W_;
constexpr int NTAU = 54;          // K = 54 taus x 32 ci = 1728 (6 segs x 9 taps)
constexpr int WCH = 128 * 36 * 2; // 9216 B per weight chunk (rows padded 32->36 bf16)

// ---- device globals (allocation-free) ----
__device__ __align__(1024) __nv_bfloat16 g_Bw[NTAU * 128 * 36];  // padded weight chunks
__device__ float g_h0[(size_t)B_ * HW_ * F_];
__device__ float g_h1[(size_t)B_ * HW_ * F_];
__device__ float g_c[(size_t)B_ * HW_ * F_];

// ---- smem map ----
// [8..40)   : 4 mbarriers (weight ring)
// [128..65664): 4 staged tiles (XH,XL,HH,HL), each 6*34 rows x 80 B = 16320 -> 16384
// [128..67712): z tile (f32, 128 px x row-stride 132) -- reuses tile region after MMA
// [68608..105472): 4 weight buffers x 9216 B
constexpr int SM_BAR  = 8;
constexpr int SM_TILE = 128;
constexpr int TILE_SZ = 16384;
constexpr int SM_Z    = 128;
constexpr int ZSTR    = 132;      // floats per z row
constexpr int SM_W    = 68608;
constexpr int SMEM_TOTAL = SM_W + 4 * WCH;   // 105472

// ---- PTX helpers ----
__device__ __forceinline__ uint32_t s2u(const void* p) {
    uint32_t a;
    asm("{ .reg .u64 t; cvta.to.shared.u64 t, %1; cvt.u32.u64 %0, t; }" : "=r"(a) : "l"(p));
    return a;
}
__device__ __forceinline__ void mbar_init(uint32_t a, uint32_t n) {
    asm volatile("mbarrier.init.shared.b64 [%0], %1;" :: "r"(a), "r"(n) : "memory");
}
__device__ __forceinline__ void mbar_expect(uint32_t a, uint32_t b) {
    asm volatile("mbarrier.arrive.expect_tx.shared.b64 _, [%0], %1;" :: "r"(a), "r"(b) : "memory");
}
__device__ __forceinline__ void mbar_wait(uint32_t a, uint32_t ph) {
    asm volatile(
        "{\n\t.reg .pred P;\n\t"
        "W_%=:\n\t"
        "mbarrier.try_wait.parity.shared.b64 P, [%0], %1, 0x989680;\n\t"
        "@!P bra W_%=;\n\t}"
        :: "r"(a), "r"(ph) : "memory");
}
__device__ __forceinline__ void bulk_cp(uint32_t dst, const void* src, uint32_t bytes, uint32_t bar) {
    asm volatile(
        "cp.async.bulk.shared::cta.global.mbarrier::complete_tx::bytes [%0], [%1], %2, [%3];"
        :: "r"(dst), "l"(src), "r"(bytes), "r"(bar) : "memory");
}
__device__ __forceinline__ void ldmatrix4(uint32_t* a, uint32_t addr) {
    asm volatile("ldmatrix.sync.aligned.m8n8.x4.shared.b16 {%0,%1,%2,%3}, [%4];"
                 : "=r"(a[0]), "=r"(a[1]), "=r"(a[2]), "=r"(a[3]) : "r"(addr));
}
__device__ __forceinline__ void mma16816(float* d, const uint32_t* a, uint32_t b0, uint32_t b1) {
    asm volatile(
        "mma.sync.aligned.m16n8k16.row.col.f32.bf16.bf16.f32 "
        "{%0,%1,%2,%3}, {%4,%5,%6,%7}, {%8,%9}, {%0,%1,%2,%3};"
        : "+f"(d[0]), "+f"(d[1]), "+f"(d[2]), "+f"(d[3])
        : "r"(a[0]), "r"(a[1]), "r"(a[2]), "r"(a[3]), "r"(b0), "r"(b1));
}
__device__ __forceinline__ __nv_bfloat16 bhi(float v) { return __float2bfloat16_rn(v); }
__device__ __forceinline__ __nv_bfloat16 blo(float v) {
    return __float2bfloat16_rn(v - __bfloat162float(__float2bfloat16_rn(v)));
}

// ---- prep: zero states + build padded weight chunks ----
// tau in [0,54): seg = tau/9, tap = tau%9. Chunk layout: [tau][n(128)][ci(36 pad)] bf16.
// B seg sources: {Wx_hi, Wx_lo, Wx_hi, Wc_hi, Wc_lo, Wc_hi}, Wc = Wx + Wh.
__global__ void prep_kernel(const float* __restrict__ Wx, const float* __restrict__ Wh) {
    int i = blockIdx.x * blockDim.x + threadIdx.x;
    if (i < B_ * HW_ * F_) { g_h0[i] = 0.f; g_c[i] = 0.f; }
    if (i < NTAU * 128 * 32) {
        int tau = i >> 12;             // /4096
        int r = i & 4095;
        int nn = r >> 5;               // cout
        int ci = r & 31;
        int seg = tau / 9;
        int tap = tau - seg * 9;
        int widx = (tap * 32 + ci) * 128 + nn;
        float wx = Wx[widx];
        float wc = wx + Wh[widx];
        __nv_bfloat16 bv;
        if (seg == 0)      bv = bhi(wx);
        else if (seg == 1) bv = blo(wx);
        else if (seg == 2) bv = bhi(wx);
        else if (seg == 3) bv = bhi(wc);
        else if (seg == 4) bv = blo(wc);
        else               bv = bhi(wc);
        g_Bw[(size_t)tau * 128 * 36 + nn * 36 + ci] = bv;
    }
}

// ---- fused step: z[128px,128gate] = im2col(x_t,h) @ W^T via mma.sync, gates fused ----
__global__ __launch_bounds__(256, 2)
void lstm_step(const float* __restrict__ x, const float* __restrict__ bias,
               float* __restrict__ out, int t) {
    extern __shared__ __align__(1024) char smem[];
    const uint32_t sb = s2u(smem);
    const int tid = threadIdx.x;
    const int wid = tid >> 5, lid = tid & 31;
    const int warp_m = wid >> 2, warp_n = wid & 3;
    const int bx = blockIdx.x, by = blockIdx.y, n = blockIdx.z;

    if (tid == 0) {
#pragma unroll
        for (int i = 0; i < 4; i++) mbar_init(sb + SM_BAR + 8 * i, 1);
    }

    const float* hin = (t & 1) ? g_h1 : g_h0;
    float* hout      = (t & 1) ? g_h0 : g_h1;
    const float* xim = x + ((size_t)(n * T_ + t) * HW_) * C_;
    const float* him = hin + (size_t)n * HW_ * C_;

    // stage x,h halo tiles (6 rows x 34 cols x 32 ci), bf16 hi/lo, row stride 80 B
    for (int idx = tid; idx < 6 * 34 * 8; idx += 256) {
        int r = idx / (34 * 8);
        int rem = idx - r * (34 * 8);
        int cx = rem >> 3, c4 = rem & 7;
        int gy = by * 4 - 1 + r, gx = bx * 32 - 1 + cx;
        float4 xv = make_float4(0.f, 0.f, 0.f, 0.f), hv = xv;
        if ((unsigned)gy < (unsigned)H_ && (unsigned)gx < (unsigned)W_) {
            size_t o = ((size_t)gy * W_ + gx) * C_ + c4 * 4;
            xv = *(const float4*)(xim + o);
            hv = *(const float4*)(him + o);
        }
        int eb = (r * 34 + cx) * 80 + c4 * 8;  // byte offset inside a tile
        char* p0 = smem + SM_TILE + eb;
        *(__nv_bfloat162*)(p0)                    = __halves2bfloat162(bhi(xv.x), bhi(xv.y));
        *(__nv_bfloat162*)(p0 + 4)                = __halves2bfloat162(bhi(xv.z), bhi(xv.w));
        *(__nv_bfloat162*)(p0 + TILE_SZ)          = __halves2bfloat162(blo(xv.x), blo(xv.y));
        *(__nv_bfloat162*)(p0 + TILE_SZ + 4)      = __halves2bfloat162(blo(xv.z), blo(xv.w));
        *(__nv_bfloat162*)(p0 + 2 * TILE_SZ)      = __halves2bfloat162(bhi(hv.x), bhi(hv.y));
        *(__nv_bfloat162*)(p0 + 2 * TILE_SZ + 4)  = __halves2bfloat162(bhi(hv.z), bhi(hv.w));
        *(__nv_bfloat162*)(p0 + 3 * TILE_SZ)      = __halves2bfloat162(blo(hv.x), blo(hv.y));
        *(__nv_bfloat162*)(p0 + 3 * TILE_SZ + 4)  = __halves2bfloat162(blo(hv.z), blo(hv.w));
    }
    __syncthreads();

    // prologue: prefetch 4 weight chunks
    if (tid == 0) {
#pragma unroll
        for (int i = 0; i < 4; i++) {
            mbar_expect(sb + SM_BAR + 8 * i, WCH);
            bulk_cp(sb + SM_W + i * WCH, (const char*)g_Bw + (size_t)i * WCH,
                    WCH, sb + SM_BAR + 8 * i);
        }
    }

    // per-lane constant addresses
    const int row_in_tile = ((lid >> 3) & 1) * 8 + (lid & 7);
    const int khalf = lid >> 4;
    uint32_t amt[4];
#pragma unroll
    for (int mt = 0; mt < 4; mt++) {
        int p = warp_m * 64 + mt * 16 + row_in_tile;
        amt[mt] = ((p >> 5) * 34 + (p & 31)) * 80 + khalf * 16;
    }
    uint32_t bmt[4];
#pragma unroll
    for (int nt = 0; nt < 4; nt++)
        bmt[nt] = (warp_n * 32 + nt * 8 + (lid >> 2)) * 72 + (lid & 3) * 4;

    float d[4][4][4];
#pragma unroll
    for (int mt = 0; mt < 4; mt++)
#pragma unroll
        for (int nt = 0; nt < 4; nt++)
#pragma unroll
            for (int q = 0; q < 4; q++) d[mt][nt][q] = 0.f;

    // main loop over 54 taus (K=32 each -> two k16 steps)
    for (int tau = 0; tau < NTAU; tau++) {
        const int b = tau & 3;
        mbar_wait(sb + SM_BAR + 8 * b, (tau >> 2) & 1);

        int seg = tau / 9;
        int tap = tau - seg * 9;
        int dy = tap / 3, dx = tap - dy * 3;
        // A segs: 0->XH, 1->XH, 2->XL, 3->HH, 4->HH, 5->HL
        uint32_t toff = SM_TILE + (seg >= 3 ? 2 * TILE_SZ : 0) +
                        ((seg == 2 || seg == 5) ? TILE_SZ : 0);
        uint32_t abase = sb + toff + (dy * 34 + dx) * 80;
        const char* wp = smem + SM_W + b * WCH;

#pragma unroll
        for (int s = 0; s < 2; s++) {
            uint32_t af[4][4];
#pragma unroll
            for (int mt = 0; mt < 4; mt++)
                ldmatrix4(af[mt], abase + amt[mt] + s * 32);
#pragma unroll
            for (int nt = 0; nt < 4; nt++) {
                uint32_t b0 = *(const uint32_t*)(wp + bmt[nt] + s * 32);
                uint32_t b1 = *(const uint32_t*)(wp + bmt[nt] + s * 32 + 16);
#pragma unroll
                for (int mt = 0; mt < 4; mt++)
                    mma16816(d[mt][nt], af[mt], b0, b1);
            }
        }
        __syncthreads();  // all warps done with buffer b before reuse
        if (tid == 0 && tau + 4 < NTAU) {
            mbar_expect(sb + SM_BAR + 8 * b, WCH);
            bulk_cp(sb + SM_W + b * WCH, (const char*)g_Bw + (size_t)(tau + 4) * WCH,
                    WCH, sb + SM_BAR + 8 * b);
        }
    }

    // stage z to smem (tiles no longer needed)
    float* zb = (float*)(smem + SM_Z);
#pragma unroll
    for (int mt = 0; mt < 4; mt++) {
        int prow = warp_m * 64 + mt * 16 + (lid >> 2);
#pragma unroll
        for (int nt = 0; nt < 4; nt++) {
            int col = warp_n * 32 + nt * 8 + 2 * (lid & 3);
            *(float2*)(zb + prow * ZSTR + col)       = make_float2(d[mt][nt][0], d[mt][nt][1]);
            *(float2*)(zb + (prow + 8) * ZSTR + col) = make_float2(d[mt][nt][2], d[mt][nt][3]);
        }
    }
    __syncthreads();

    // gates + state update; coalesced float4 I/O
#pragma unroll
    for (int j = 0; j < 4; j++) {
        int idx = j * 256 + tid;          // 1024 = 128 px * 8 f-groups
        int p = idx >> 3, fg = idx & 7;
        int gy = by * 4 + (p >> 5), gx = bx * 32 + (p & 31);
        const float* zr = zb + p * ZSTR + fg * 4;
        float4 zi = *(const float4*)(zr);
        float4 zf = *(const float4*)(zr + 32);
        float4 zc = *(const float4*)(zr + 64);
        float4 zo = *(const float4*)(zr + 96);
        float4 bi = *(const float4*)(bias + fg * 4);
        float4 bf = *(const float4*)(bias + 32 + fg * 4);
        float4 bc = *(const float4*)(bias + 64 + fg * 4);
        float4 bo = *(const float4*)(bias + 96 + fg * 4);
        size_t sbase = ((size_t)n * HW_ + (size_t)gy * W_ + gx) * F_ + fg * 4;
        float4 cold = *(const float4*)(g_c + sbase);

        float vi[4] = {zi.x + bi.x, zi.y + bi.y, zi.z + bi.z, zi.w + bi.w};
        float vf[4] = {zf.x + bf.x, zf.y + bf.y, zf.z + bf.z, zf.w + bf.w};
        float vc[4] = {zc.x + bc.x, zc.y + bc.y, zc.z + bc.z, zc.w + bc.w};
        float vo[4] = {zo.x + bo.x, zo.y + bo.y, zo.z + bo.z, zo.w + bo.w};
        const float* cp = (const float*)&cold;
        float cn[4], hn[4];
#pragma unroll
        for (int q = 0; q < 4; q++) {
            float ig = __saturatef(fmaf(0.2f, vi[q], 0.5f));
            float fgt = __saturatef(fmaf(0.2f, vf[q], 0.5f));
            float og = __saturatef(fmaf(0.2f, vo[q], 0.5f));
            float cv = fmaf(fgt, cp[q], ig * tanhf(vc[q]));
            cn[q] = cv;
            hn[q] = og * tanhf(cv);
        }
        float* outp = out + ((size_t)(n * T_ + t) * HW_ + (size_t)gy * W_ + gx) * F_ + fg * 4;
        *(float4*)(g_c + sbase)  = *(const float4*)(cn);
        *(float4*)(hout + sbase) = *(const float4*)(hn);
        *(float4*)(outp)         = *(const float4*)(hn);
    }
}

extern "C" void kernel_launch(void* const* d_in, const int* in_sizes, int n_in,
                              void* d_out, int out_size) {
    const float* x  = (const float*)d_in[0];
    const float* Wx = (const float*)d_in[1];
    const float* Wh = (const float*)d_in[2];
    const float* b  = (const float*)d_in[3];
    float* out = (float*)d_out;

    static bool attr_set = false;
    if (!attr_set) {
        cudaFuncSetAttribute(lstm_step, cudaFuncAttributeMaxDynamicSharedMemorySize,
                             SMEM_TOTAL);
        attr_set = true;
    }

    prep_kernel<<<(B_ * HW_ * F_ + 255) / 256, 256>>>(Wx, Wh);
    for (int t = 0; t < T_; t++)
        lstm_step<<<dim3(W_ / 32, H_ / 4, B_), 256, SMEM_TOTAL>>>(x, b, out, t);
}

// round 8
// speedup vs baseline: 24.3361x; 1.7210x over previous
#include <cuda_runtime.h>
#include <cuda_fp16.h>
#include <cstdint>

constexpr int B_ = 8, T_ = 12, H_ = 96, W_ = 96, C_ = 32, F_ = 32;
constexpr int HW_ = H_ * W_;
constexpr int NTAP = 9;
constexpr int WPAD = 40;             // fp16 per weight row (80 B, 16B-aligned rows)
constexpr int CHB  = 128 * WPAD * 2; // 10240 B per weight chunk
constexpr int TAPB = 4 * CHB;        // 40960 B per tap stage (Wx_hi, Wx_lo, Wc_hi, Wc_lo)

// ---- device globals (allocation-free) ----
__device__ __align__(1024) __half g_Bw[NTAP * 4 * 128 * WPAD];  // pre-scaled (x32) weights
__device__ float g_h0[(size_t)B_ * HW_ * F_];
__device__ float g_h1[(size_t)B_ * HW_ * F_];
__device__ float g_c[(size_t)B_ * HW_ * F_];

// ---- smem map ----
constexpr int SM_FULL  = 8;      // full[2] @ 8,16
constexpr int SM_EMPTY = 24;     // empty[2] @ 24,32
constexpr int SM_X    = 128;                 // fp16(x)*2^-5 tile, 6*34 rows x 80 B
constexpr int SM_H    = SM_X + 16384;        // fp16(h)*2^-5 tile
constexpr int SM_W    = SM_H + 16384;        // ring: 2 stages x 40960
constexpr int SMEM_TOTAL = SM_W + 2 * TAPB;  // 114816 (still 2 CTAs/SM)
constexpr int SM_Z    = 128;                 // z tile overlaps tiles+ring after MMA
constexpr int ZSTR    = 132;

// ---- PTX helpers ----
__device__ __forceinline__ uint32_t s2u(const void* p) {
    uint32_t a;
    asm("{ .reg .u64 t; cvta.to.shared.u64 t, %1; cvt.u32.u64 %0, t; }" : "=r"(a) : "l"(p));
    return a;
}
__device__ __forceinline__ void mbar_init(uint32_t a, uint32_t n) {
    asm volatile("mbarrier.init.shared.b64 [%0], %1;" :: "r"(a), "r"(n) : "memory");
}
__device__ __forceinline__ void mbar_expect(uint32_t a, uint32_t b) {
    asm volatile("mbarrier.arrive.expect_tx.shared.b64 _, [%0], %1;" :: "r"(a), "r"(b) : "memory");
}
__device__ __forceinline__ void mbar_arrive(uint32_t a) {
    asm volatile("mbarrier.arrive.shared.b64 _, [%0];" :: "r"(a) : "memory");
}
__device__ __forceinline__ void mbar_wait(uint32_t a, uint32_t ph) {
    asm volatile(
        "{\n\t.reg .pred P;\n\t"
        "W_%=:\n\t"
        "mbarrier.try_wait.parity.shared.b64 P, [%0], %1, 0x989680;\n\t"
        "@!P bra W_%=;\n\t}"
        :: "r"(a), "r"(ph) : "memory");
}
__device__ __forceinline__ void bulk_cp(uint32_t dst, const void* src, uint32_t bytes, uint32_t bar) {
    asm volatile(
        "cp.async.bulk.shared::cta.global.mbarrier::complete_tx::bytes [%0], [%1], %2, [%3];"
        :: "r"(dst), "l"(src), "r"(bytes), "r"(bar) : "memory");
}
__device__ __forceinline__ void ldmatrix4(uint32_t* a, uint32_t addr) {
    asm volatile("ldmatrix.sync.aligned.m8n8.x4.shared.b16 {%0,%1,%2,%3}, [%4];"
                 : "=r"(a[0]), "=r"(a[1]), "=r"(a[2]), "=r"(a[3]) : "r"(addr));
}
__device__ __forceinline__ void mma16816(float* d, const uint32_t* a, uint32_t b0, uint32_t b1) {
    asm volatile(
        "mma.sync.aligned.m16n8k16.row.col.f32.f16.f16.f32 "
        "{%0,%1,%2,%3}, {%4,%5,%6,%7}, {%8,%9}, {%0,%1,%2,%3};"
        : "+f"(d[0]), "+f"(d[1]), "+f"(d[2]), "+f"(d[3])
        : "r"(a[0]), "r"(a[1]), "r"(a[2]), "r"(a[3]), "r"(b0), "r"(b1));
}

// ---- prep: zero states + build pre-scaled fp16 weight stages ----
// g_Bw[tap][src][n:128][ci:WPAD]; src: 0=Wx_hi*32, 1=Wx_lo*32, 2=Wc_hi*32, 3=Wc_lo*32
// hi = fp16(w); lo = w - (float)hi; both stored *32 (exact pow2) so lo stays normal.
__global__ void prep_kernel(const float* __restrict__ Wx, const float* __restrict__ Wh) {
    int i = blockIdx.x * blockDim.x + threadIdx.x;
    if (i < B_ * HW_ * F_) { g_h0[i] = 0.f; g_c[i] = 0.f; }
    if (i < NTAP * 4 * 128 * 32) {
        int tap = i >> 14;             // /16384
        int r = i & 16383;
        int src = r >> 12;
        int rr = r & 4095;
        int nn = rr >> 5;              // cout
        int ci = rr & 31;
        int widx = (tap * 32 + ci) * 128 + nn;
        float w = (src < 2) ? Wx[widx] : (Wx[widx] + Wh[widx]);
        float hi = (float)__float2half_rn(w);
        float v = (src & 1) ? (w - hi) * 32.0f : hi * 32.0f;
        g_Bw[(size_t)tap * (4 * 128 * WPAD) + src * (128 * WPAD) + nn * WPAD + ci] =
            __float2half_rn(v);
    }
}

// ---- fused step: z[128px,128gate] = [x,h]_fp16 @ [W_hi,W_lo]^T via mma.sync ----
__global__ __launch_bounds__(256, 2)
void lstm_step(const float* __restrict__ x, const float* __restrict__ bias,
               float* __restrict__ out, int t) {
    extern __shared__ __align__(1024) char smem[];
    const uint32_t sb = s2u(smem);
    const int tid = threadIdx.x;
    const int wid = tid >> 5, lid = tid & 31;
    const int warp_m = wid >> 2, warp_n = wid & 3;
    const int bx = blockIdx.x, by = blockIdx.y, n = blockIdx.z;

    if (tid == 0) {
        mbar_init(sb + SM_FULL + 0, 1);
        mbar_init(sb + SM_FULL + 8, 1);
        mbar_init(sb + SM_EMPTY + 0, 8);
        mbar_init(sb + SM_EMPTY + 8, 8);
    }
    __syncthreads();

    // prologue: prefetch tap 0 and tap 1 weight stages
    if (tid == 0) {
        mbar_expect(sb + SM_FULL + 0, TAPB);
        bulk_cp(sb + SM_W, (const char*)g_Bw, TAPB, sb + SM_FULL + 0);
        mbar_expect(sb + SM_FULL + 8, TAPB);
        bulk_cp(sb + SM_W + TAPB, (const char*)g_Bw + TAPB, TAPB, sb + SM_FULL + 8);
    }

    const float* hin = (t & 1) ? g_h1 : g_h0;
    float* hout      = (t & 1) ? g_h0 : g_h1;
    const float* xim = x + ((size_t)(n * T_ + t) * HW_) * C_;
    const float* him = hin + (size_t)n * HW_ * C_;

    // stage x,h halo tiles (6 rows x 34 cols x 32 ci) fp16 * 2^-5, row stride 80 B
    for (int idx = tid; idx < 6 * 34 * 8; idx += 256) {
        int r = idx / (34 * 8);
        int rem = idx - r * (34 * 8);
        int cx = rem >> 3, c4 = rem & 7;
        int gy = by * 4 - 1 + r, gx = bx * 32 - 1 + cx;
        float4 xv = make_float4(0.f, 0.f, 0.f, 0.f), hv = xv;
        if ((unsigned)gy < (unsigned)H_ && (unsigned)gx < (unsigned)W_) {
            size_t o = ((size_t)gy * W_ + gx) * C_ + c4 * 4;
            xv = *(const float4*)(xim + o);
            hv = *(const float4*)(him + o);
        }
        const float sc = 0.03125f;  // 2^-5
        int eb = (r * 34 + cx) * 80 + c4 * 8;
        char* px_ = smem + SM_X + eb;
        char* ph_ = smem + SM_H + eb;
        *(__half2*)(px_)     = __halves2half2(__float2half_rn(xv.x * sc), __float2half_rn(xv.y * sc));
        *(__half2*)(px_ + 4) = __halves2half2(__float2half_rn(xv.z * sc), __float2half_rn(xv.w * sc));
        *(__half2*)(ph_)     = __halves2half2(__float2half_rn(hv.x * sc), __float2half_rn(hv.y * sc));
        *(__half2*)(ph_ + 4) = __halves2half2(__float2half_rn(hv.z * sc), __float2half_rn(hv.w * sc));
    }
    __syncthreads();

    // per-lane constant offsets
    const int row_in_tile = ((lid >> 3) & 1) * 8 + (lid & 7);
    const int khalf = lid >> 4;
    uint32_t amt[4];
#pragma unroll
    for (int mt = 0; mt < 4; mt++) {
        int p = warp_m * 64 + mt * 16 + row_in_tile;
        amt[mt] = ((p >> 5) * 34 + (p & 31)) * 80 + khalf * 16;
    }
    // B ldmatrix.x4: matrix m=lid>>3 -> nt = 2q+(m>>1), k-half byte offset (m&1)*16
    const int m3 = lid >> 3;
    uint32_t bq[2];
#pragma unroll
    for (int q = 0; q < 2; q++)
        bq[q] = (uint32_t)((warp_n * 32 + (2 * q + (m3 >> 1)) * 8 + (lid & 7)) * (WPAD * 2) +
                           (m3 & 1) * 16);

    float d[4][4][4];
#pragma unroll
    for (int mt = 0; mt < 4; mt++)
#pragma unroll
        for (int nt = 0; nt < 4; nt++)
#pragma unroll
            for (int q = 0; q < 4; q++) d[mt][nt][q] = 0.f;

    // main loop over 9 taps; per tap: X part (Wx_hi,Wx_lo) then H part (Wc_hi,Wc_lo)
    for (int tap = 0; tap < NTAP; tap++) {
        const int b = tap & 1;
        const uint32_t fullb = sb + SM_FULL + 8 * b;
        mbar_wait(fullb, (tap >> 1) & 1);

        const int dy = tap / 3, dx = tap - dy * 3;
        const uint32_t wbase = sb + SM_W + b * TAPB;
        const uint32_t aoff = (dy * 34 + dx) * 80;

#pragma unroll
        for (int part = 0; part < 2; part++) {
            const uint32_t abase = sb + (part ? SM_H : SM_X) + aoff;
            const uint32_t wph = wbase + part * 2 * CHB;  // hi chunk
            const uint32_t wpl = wph + CHB;               // lo chunk
#pragma unroll
            for (int s = 0; s < 2; s++) {
                uint32_t af[4][4];
#pragma unroll
                for (int mt = 0; mt < 4; mt++)
                    ldmatrix4(af[mt], abase + amt[mt] + s * 32);
                uint32_t bh[2][4], bl[2][4];
#pragma unroll
                for (int q = 0; q < 2; q++) ldmatrix4(bh[q], wph + bq[q] + s * 32);
#pragma unroll
                for (int q = 0; q < 2; q++) ldmatrix4(bl[q], wpl + bq[q] + s * 32);
#pragma unroll
                for (int nt = 0; nt < 4; nt++) {
                    uint32_t b0 = bh[nt >> 1][(nt & 1) * 2];
                    uint32_t b1 = bh[nt >> 1][(nt & 1) * 2 + 1];
#pragma unroll
                    for (int mt = 0; mt < 4; mt++) mma16816(d[mt][nt], af[mt], b0, b1);
                }
#pragma unroll
                for (int nt = 0; nt < 4; nt++) {
                    uint32_t b0 = bl[nt >> 1][(nt & 1) * 2];
                    uint32_t b1 = bl[nt >> 1][(nt & 1) * 2 + 1];
#pragma unroll
                    for (int mt = 0; mt < 4; mt++) mma16816(d[mt][nt], af[mt], b0, b1);
                }
            }
        }

        if (lid == 0) mbar_arrive(sb + SM_EMPTY + 8 * b);   // this warp done with stage b
        if (tid == 0 && tap + 2 < NTAP) {
            mbar_wait(sb + SM_EMPTY + 8 * b, (tap >> 1) & 1);  // all 8 warps done
            mbar_expect(fullb, TAPB);
            bulk_cp(sb + SM_W + b * TAPB, (const char*)g_Bw + (size_t)(tap + 2) * TAPB,
                    TAPB, fullb);
        }
    }
    __syncthreads();  // ring/tiles dead -> safe to overwrite with z

    // stage z to smem
    float* zb = (float*)(smem + SM_Z);
#pragma unroll
    for (int mt = 0; mt < 4; mt++) {
        int prow = warp_m * 64 + mt * 16 + (lid >> 2);
#pragma unroll
        for (int nt = 0; nt < 4; nt++) {
            int col = warp_n * 32 + nt * 8 + 2 * (lid & 3);
            *(float2*)(zb + prow * ZSTR + col)       = make_float2(d[mt][nt][0], d[mt][nt][1]);
            *(float2*)(zb + (prow + 8) * ZSTR + col) = make_float2(d[mt][nt][2], d[mt][nt][3]);
        }
    }
    __syncthreads();

    // gates + state update; coalesced float4 I/O
#pragma unroll
    for (int j = 0; j < 4; j++) {
        int idx = j * 256 + tid;          // 1024 = 128 px * 8 f-groups
        int p = idx >> 3, fg = idx & 7;
        int gy = by * 4 + (p >> 5), gx = bx * 32 + (p & 31);
        const float* zr = zb + p * ZSTR + fg * 4;
        float4 zi = *(const float4*)(zr);
        float4 zf = *(const float4*)(zr + 32);
        float4 zc = *(const float4*)(zr + 64);
        float4 zo = *(const float4*)(zr + 96);
        float4 bi = *(const float4*)(bias + fg * 4);
        float4 bf = *(const float4*)(bias + 32 + fg * 4);
        float4 bc = *(const float4*)(bias + 64 + fg * 4);
        float4 bo = *(const float4*)(bias + 96 + fg * 4);
        size_t sbase = ((size_t)n * HW_ + (size_t)gy * W_ + gx) * F_ + fg * 4;
        float4 cold = *(const float4*)(g_c + sbase);

        float vi[4] = {zi.x + bi.x, zi.y + bi.y, zi.z + bi.z, zi.w + bi.w};
        float vf[4] = {zf.x + bf.x, zf.y + bf.y, zf.z + bf.z, zf.w + bf.w};
        float vc[4] = {zc.x + bc.x, zc.y + bc.y, zc.z + bc.z, zc.w + bc.w};
        float vo[4] = {zo.x + bo.x, zo.y + bo.y, zo.z + bo.z, zo.w + bo.w};
        const float* cp = (const float*)&cold;
        float cn[4], hn[4];
#pragma unroll
        for (int q = 0; q < 4; q++) {
            float ig = __saturatef(fmaf(0.2f, vi[q], 0.5f));
            float fgt = __saturatef(fmaf(0.2f, vf[q], 0.5f));
            float og = __saturatef(fmaf(0.2f, vo[q], 0.5f));
            float cv = fmaf(fgt, cp[q], ig * tanhf(vc[q]));
            cn[q] = cv;
            hn[q] = og * tanhf(cv);
        }
        float* outp = out + ((size_t)(n * T_ + t) * HW_ + (size_t)gy * W_ + gx) * F_ + fg * 4;
        *(float4*)(g_c + sbase)  = *(const float4*)(cn);
        *(float4*)(hout + sbase) = *(const float4*)(hn);
        *(float4*)(outp)         = *(const float4*)(hn);
    }
}

extern "C" void kernel_launch(void* const* d_in, const int* in_sizes, int n_in,
                              void* d_out, int out_size) {
    const float* x  = (const float*)d_in[0];
    const float* Wx = (const float*)d_in[1];
    const float* Wh = (const float*)d_in[2];
    const float* b  = (const float*)d_in[3];
    float* out = (float*)d_out;

    static bool attr_set = false;
    if (!attr_set) {
        cudaFuncSetAttribute(lstm_step, cudaFuncAttributeMaxDynamicSharedMemorySize,
                             SMEM_TOTAL);
        attr_set = true;
    }

    prep_kernel<<<(B_ * HW_ * F_ + 255) / 256, 256>>>(Wx, Wh);
    for (int t = 0; t < T_; t++)
        lstm_step<<<dim3(W_ / 32, H_ / 4, B_), 256, SMEM_TOTAL>>>(x, b, out, t);
}

// round 9
// speedup vs baseline: 36.7377x; 1.5096x over previous
#include <cuda_runtime.h>
#include <cuda_fp16.h>
#include <cstdint>

constexpr int B_ = 8, T_ = 12, H_ = 96, W_ = 96, C_ = 32, F_ = 32;
constexpr int HW_ = H_ * W_;
constexpr int NTAP = 9;
constexpr int WPAD = 40;             // fp16 per weight row (80 B, 16B-aligned rows)
constexpr int CHB  = 128 * WPAD * 2; // 10240 B per weight chunk
constexpr int TAPB = 2 * CHB;        // 20480 B per tap stage (Wx, Wc)
constexpr int NSTAGE = 4;            // ring depth

// ---- device globals (allocation-free) ----
__device__ __align__(1024) __half g_Bw[NTAP * 2 * 128 * WPAD];  // fp16 weights
__device__ float g_h0[(size_t)B_ * HW_ * F_];
__device__ float g_h1[(size_t)B_ * HW_ * F_];
__device__ float g_c[(size_t)B_ * HW_ * F_];

// ---- smem map ----
constexpr int SM_FULL  = 8;                  // full[4]  @ 8..40
constexpr int SM_EMPTY = 40;                 // empty[4] @ 40..72
constexpr int SM_X    = 128;                 // fp16(x) tile, 6*34 rows x 80 B
constexpr int SM_H    = SM_X + 16384;        // fp16(h) tile
constexpr int SM_W    = SM_H + 16384;        // ring: 4 stages x 20480
constexpr int SMEM_TOTAL = SM_W + NSTAGE * TAPB;  // 114816 (2 CTAs/SM)
constexpr int SM_Z    = 128;                 // z tile overlaps tiles+ring after MMA
constexpr int ZSTR    = 132;

// ---- PTX helpers ----
__device__ __forceinline__ uint32_t s2u(const void* p) {
    uint32_t a;
    asm("{ .reg .u64 t; cvta.to.shared.u64 t, %1; cvt.u32.u64 %0, t; }" : "=r"(a) : "l"(p));
    return a;
}
__device__ __forceinline__ void mbar_init(uint32_t a, uint32_t n) {
    asm volatile("mbarrier.init.shared.b64 [%0], %1;" :: "r"(a), "r"(n) : "memory");
}
__device__ __forceinline__ void mbar_expect(uint32_t a, uint32_t b) {
    asm volatile("mbarrier.arrive.expect_tx.shared.b64 _, [%0], %1;" :: "r"(a), "r"(b) : "memory");
}
__device__ __forceinline__ void mbar_arrive(uint32_t a) {
    asm volatile("mbarrier.arrive.shared.b64 _, [%0];" :: "r"(a) : "memory");
}
__device__ __forceinline__ void mbar_wait(uint32_t a, uint32_t ph) {
    asm volatile(
        "{\n\t.reg .pred P;\n\t"
        "W_%=:\n\t"
        "mbarrier.try_wait.parity.shared.b64 P, [%0], %1, 0x989680;\n\t"
        "@!P bra W_%=;\n\t}"
        :: "r"(a), "r"(ph) : "memory");
}
__device__ __forceinline__ void bulk_cp(uint32_t dst, const void* src, uint32_t bytes, uint32_t bar) {
    asm volatile(
        "cp.async.bulk.shared::cta.global.mbarrier::complete_tx::bytes [%0], [%1], %2, [%3];"
        :: "r"(dst), "l"(src), "r"(bytes), "r"(bar) : "memory");
}
__device__ __forceinline__ void ldmatrix4(uint32_t* a, uint32_t addr) {
    asm volatile("ldmatrix.sync.aligned.m8n8.x4.shared.b16 {%0,%1,%2,%3}, [%4];"
                 : "=r"(a[0]), "=r"(a[1]), "=r"(a[2]), "=r"(a[3]) : "r"(addr));
}
__device__ __forceinline__ void mma16816(float* d, const uint32_t* a, uint32_t b0, uint32_t b1) {
    asm volatile(
        "mma.sync.aligned.m16n8k16.row.col.f32.f16.f16.f32 "
        "{%0,%1,%2,%3}, {%4,%5,%6,%7}, {%8,%9}, {%0,%1,%2,%3};"
        : "+f"(d[0]), "+f"(d[1]), "+f"(d[2]), "+f"(d[3])
        : "r"(a[0]), "r"(a[1]), "r"(a[2]), "r"(a[3]), "r"(b0), "r"(b1));
}

// ---- prep: zero states + build fp16 weight stages ----
// g_Bw[tap][src][n:128][ci:WPAD]; src: 0 = Wx, 1 = Wc = Wx + Wh   (plain fp16)
__global__ void prep_kernel(const float* __restrict__ Wx, const float* __restrict__ Wh) {
    int i = blockIdx.x * blockDim.x + threadIdx.x;
    if (i < B_ * HW_ * F_) { g_h0[i] = 0.f; g_c[i] = 0.f; }
    if (i < NTAP * 2 * 128 * 32) {
        int tap = i >> 13;             // /8192
        int r = i & 8191;
        int src = r >> 12;
        int rr = r & 4095;
        int nn = rr >> 5;              // cout
        int ci = rr & 31;
        int widx = (tap * 32 + ci) * 128 + nn;
        float w = (src == 0) ? Wx[widx] : (Wx[widx] + Wh[widx]);
        g_Bw[(size_t)tap * (2 * 128 * WPAD) + src * (128 * WPAD) + nn * WPAD + ci] =
            __float2half_rn(w);
    }
}

// ---- fused step: z[128px,128gate] = [x,h]_fp16 @ [Wx,Wc]^T via mma.sync ----
__global__ __launch_bounds__(256, 2)
void lstm_step(const float* __restrict__ x, const float* __restrict__ bias,
               float* __restrict__ out, int t) {
    extern __shared__ __align__(1024) char smem[];
    const uint32_t sb = s2u(smem);
    const int tid = threadIdx.x;
    const int wid = tid >> 5, lid = tid & 31;
    const int warp_m = wid >> 2, warp_n = wid & 3;
    const int bx = blockIdx.x, by = blockIdx.y, n = blockIdx.z;

    if (tid == 0) {
#pragma unroll
        for (int i = 0; i < NSTAGE; i++) {
            mbar_init(sb + SM_FULL + 8 * i, 1);
            mbar_init(sb + SM_EMPTY + 8 * i, 8);
        }
    }
    __syncthreads();

    // prologue: prefetch taps 0..3
    if (tid == 0) {
#pragma unroll
        for (int i = 0; i < NSTAGE; i++) {
            mbar_expect(sb + SM_FULL + 8 * i, TAPB);
            bulk_cp(sb + SM_W + i * TAPB, (const char*)g_Bw + (size_t)i * TAPB,
                    TAPB, sb + SM_FULL + 8 * i);
        }
    }

    const float* hin = (t & 1) ? g_h1 : g_h0;
    float* hout      = (t & 1) ? g_h0 : g_h1;
    const float* xim = x + ((size_t)(n * T_ + t) * HW_) * C_;
    const float* him = hin + (size_t)n * HW_ * C_;

    // stage x,h halo tiles (6 rows x 34 cols x 32 ci) fp16, row stride 80 B
    for (int idx = tid; idx < 6 * 34 * 8; idx += 256) {
        int r = idx / (34 * 8);
        int rem = idx - r * (34 * 8);
        int cx = rem >> 3, c4 = rem & 7;
        int gy = by * 4 - 1 + r, gx = bx * 32 - 1 + cx;
        float4 xv = make_float4(0.f, 0.f, 0.f, 0.f), hv = xv;
        if ((unsigned)gy < (unsigned)H_ && (unsigned)gx < (unsigned)W_) {
            size_t o = ((size_t)gy * W_ + gx) * C_ + c4 * 4;
            xv = *(const float4*)(xim + o);
            hv = *(const float4*)(him + o);
        }
        int eb = (r * 34 + cx) * 80 + c4 * 8;
        char* px_ = smem + SM_X + eb;
        char* ph_ = smem + SM_H + eb;
        *(__half2*)(px_)     = __halves2half2(__float2half_rn(xv.x), __float2half_rn(xv.y));
        *(__half2*)(px_ + 4) = __halves2half2(__float2half_rn(xv.z), __float2half_rn(xv.w));
        *(__half2*)(ph_)     = __halves2half2(__float2half_rn(hv.x), __float2half_rn(hv.y));
        *(__half2*)(ph_ + 4) = __halves2half2(__float2half_rn(hv.z), __float2half_rn(hv.w));
    }
    __syncthreads();

    // per-lane constant offsets
    const int row_in_tile = ((lid >> 3) & 1) * 8 + (lid & 7);
    const int khalf = lid >> 4;
    uint32_t amt[4];
#pragma unroll
    for (int mt = 0; mt < 4; mt++) {
        int p = warp_m * 64 + mt * 16 + row_in_tile;
        amt[mt] = ((p >> 5) * 34 + (p & 31)) * 80 + khalf * 16;
    }
    // B ldmatrix.x4: matrix m=lid>>3 -> nt = 2q+(m>>1), k-half byte offset (m&1)*16
    const int m3 = lid >> 3;
    uint32_t bq[2];
#pragma unroll
    for (int q = 0; q < 2; q++)
        bq[q] = (uint32_t)((warp_n * 32 + (2 * q + (m3 >> 1)) * 8 + (lid & 7)) * (WPAD * 2) +
                           (m3 & 1) * 16);

    float d[4][4][4];
#pragma unroll
    for (int mt = 0; mt < 4; mt++)
#pragma unroll
        for (int nt = 0; nt < 4; nt++)
#pragma unroll
            for (int q = 0; q < 4; q++) d[mt][nt][q] = 0.f;

    // main loop over 9 taps; per tap: x @ Wx, then h @ Wc
    for (int tap = 0; tap < NTAP; tap++) {
        const int b = tap & 3;
        const uint32_t fullb = sb + SM_FULL + 8 * b;
        mbar_wait(fullb, (tap >> 2) & 1);

        const int dy = tap / 3, dx = tap - dy * 3;
        const uint32_t wbase = sb + SM_W + b * TAPB;
        const uint32_t aoff = (dy * 34 + dx) * 80;

#pragma unroll
        for (int part = 0; part < 2; part++) {
            const uint32_t abase = sb + (part ? SM_H : SM_X) + aoff;
            const uint32_t wp = wbase + part * CHB;
#pragma unroll
            for (int s = 0; s < 2; s++) {
                uint32_t af[4][4];
#pragma unroll
                for (int mt = 0; mt < 4; mt++)
                    ldmatrix4(af[mt], abase + amt[mt] + s * 32);
                uint32_t bh[2][4];
#pragma unroll
                for (int q = 0; q < 2; q++) ldmatrix4(bh[q], wp + bq[q] + s * 32);
#pragma unroll
                for (int nt = 0; nt < 4; nt++) {
                    uint32_t b0 = bh[nt >> 1][(nt & 1) * 2];
                    uint32_t b1 = bh[nt >> 1][(nt & 1) * 2 + 1];
#pragma unroll
                    for (int mt = 0; mt < 4; mt++) mma16816(d[mt][nt], af[mt], b0, b1);
                }
            }
        }

        if (lid == 0) mbar_arrive(sb + SM_EMPTY + 8 * b);   // this warp done with stage b
        if (tid == 0 && tap + NSTAGE < NTAP) {
            mbar_wait(sb + SM_EMPTY + 8 * b, (tap >> 2) & 1);  // all 8 warps done
            mbar_expect(fullb, TAPB);
            bulk_cp(sb + SM_W + b * TAPB, (const char*)g_Bw + (size_t)(tap + NSTAGE) * TAPB,
                    TAPB, fullb);
        }
    }
    __syncthreads();  // ring/tiles dead -> safe to overwrite with z

    // stage z to smem
    float* zb = (float*)(smem + SM_Z);
#pragma unroll
    for (int mt = 0; mt < 4; mt++) {
        int prow = warp_m * 64 + mt * 16 + (lid >> 2);
#pragma unroll
        for (int nt = 0; nt < 4; nt++) {
            int col = warp_n * 32 + nt * 8 + 2 * (lid & 3);
            *(float2*)(zb + prow * ZSTR + col)       = make_float2(d[mt][nt][0], d[mt][nt][1]);
            *(float2*)(zb + (prow + 8) * ZSTR + col) = make_float2(d[mt][nt][2], d[mt][nt][3]);
        }
    }
    __syncthreads();

    // gates + state update; coalesced float4 I/O
#pragma unroll
    for (int j = 0; j < 4; j++) {
        int idx = j * 256 + tid;          // 1024 = 128 px * 8 f-groups
        int p = idx >> 3, fg = idx & 7;
        int gy = by * 4 + (p >> 5), gx = bx * 32 + (p & 31);
        const float* zr = zb + p * ZSTR + fg * 4;
        float4 zi = *(const float4*)(zr);
        float4 zf = *(const float4*)(zr + 32);
        float4 zc = *(const float4*)(zr + 64);
        float4 zo = *(const float4*)(zr + 96);
        float4 bi = *(const float4*)(bias + fg * 4);
        float4 bf = *(const float4*)(bias + 32 + fg * 4);
        float4 bc = *(const float4*)(bias + 64 + fg * 4);
        float4 bo = *(const float4*)(bias + 96 + fg * 4);
        size_t sbase = ((size_t)n * HW_ + (size_t)gy * W_ + gx) * F_ + fg * 4;
        float4 cold = *(const float4*)(g_c + sbase);

        float vi[4] = {zi.x + bi.x, zi.y + bi.y, zi.z + bi.z, zi.w + bi.w};
        float vf[4] = {zf.x + bf.x, zf.y + bf.y, zf.z + bf.z, zf.w + bf.w};
        float vc[4] = {zc.x + bc.x, zc.y + bc.y, zc.z + bc.z, zc.w + bc.w};
        float vo[4] = {zo.x + bo.x, zo.y + bo.y, zo.z + bo.z, zo.w + bo.w};
        const float* cp = (const float*)&cold;
        float cn[4], hn[4];
#pragma unroll
        for (int q = 0; q < 4; q++) {
            float ig = __saturatef(fmaf(0.2f, vi[q], 0.5f));
            float fgt = __saturatef(fmaf(0.2f, vf[q], 0.5f));
            float og = __saturatef(fmaf(0.2f, vo[q], 0.5f));
            float cv = fmaf(fgt, cp[q], ig * tanhf(vc[q]));
            cn[q] = cv;
            hn[q] = og * tanhf(cv);
        }
        float* outp = out + ((size_t)(n * T_ + t) * HW_ + (size_t)gy * W_ + gx) * F_ + fg * 4;
        *(float4*)(g_c + sbase)  = *(const float4*)(cn);
        *(float4*)(hout + sbase) = *(const float4*)(hn);
        *(float4*)(outp)         = *(const float4*)(hn);
    }
}

extern "C" void kernel_launch(void* const* d_in, const int* in_sizes, int n_in,
                              void* d_out, int out_size) {
    const float* x  = (const float*)d_in[0];
    const float* Wx = (const float*)d_in[1];
    const float* Wh = (const float*)d_in[2];
    const float* b  = (const float*)d_in[3];
    float* out = (float*)d_out;

    static bool attr_set = false;
    if (!attr_set) {
        cudaFuncSetAttribute(lstm_step, cudaFuncAttributeMaxDynamicSharedMemorySize,
                             SMEM_TOTAL);
        attr_set = true;
    }

    prep_kernel<<<(B_ * HW_ * F_ + 255) / 256, 256>>>(Wx, Wh);
    for (int t = 0; t < T_; t++)
        lstm_step<<<dim3(W_ / 32, H_ / 4, B_), 256, SMEM_TOTAL>>>(x, b, out, t);
}